// round 16
// baseline (speedup 1.0000x reference)
#include <cuda_runtime.h>
#include <cuda_fp16.h>
#include <cstdint>
#include <cstddef>

// ---------------- problem constants ----------------
#define NB    8
#define SEQ   1024
#define DM    512
#define NH    8
#define DI    2048
#define NE    24
#define CAP   171
#define TG    2048
#define NGRP  4
#define NROWS (NB*SEQ)      // 8192
#define NTOK  (NGRP*TG)     // 8192
#define SLOTS 768
#define GOFF  192
#define EPSV  1e-6f
#define NSPLIT 4
#define KP3   1536

typedef unsigned long long u64;

// ---------------- device scratch ----------------
__device__ float  g_q[NROWS*DM];
__device__ float  g_k[NROWS*DM];
__device__ float  g_v[NROWS*DM];
__device__ float  g_tmp[NROWS*DM];
__device__ float  g_res[NROWS*DM];
__device__ __half g_resh[NROWS*DM];
__device__ float  g_part[(size_t)NSPLIT*NROWS*DM];
__device__ float  g_ml[(size_t)NSPLIT*NROWS*NH*2];
__device__ __half g_xs[(size_t)NROWS*KP3];
__device__ __half g_cs[(size_t)NROWS*KP3];
__device__ __half g_wqs[(size_t)DM*KP3];
__device__ __half g_wks[(size_t)DM*KP3];
__device__ __half g_wvs[(size_t)DM*KP3];
__device__ __half g_wos[(size_t)DM*KP3];
__device__ __half g_wh1[(size_t)NE*DI*DM];
__device__ __half g_wh2[(size_t)NE*DM*DI];
__device__ __half g_sloth[(size_t)NE*SLOTS*DI];
__device__ __half g_sloty[(size_t)NE*SLOTS*DM];
__device__ __half g_hpost[(size_t)NTOK*DI];
__device__ int    g_e1[NTOK], g_e2[NTOK], g_s1[NTOK], g_s2[NTOK];
__device__ float  g_wa[NTOK], g_wb[NTOK];
__device__ int    g_rowg[NE*SLOTS];
__device__ int    g_rowl[NE*SLOTS];
__device__ const float* g_lnp[8];

// ---------------- PTX helpers ----------------
__device__ __forceinline__ uint32_t smem_cast(const void* p) {
    uint32_t a;
    asm("{ .reg .u64 t; cvta.to.shared.u64 t, %1; cvt.u32.u64 %0, t; }" : "=r"(a) : "l"(p));
    return a;
}
#define CP_ASYNC16(dst, src) \
    asm volatile("cp.async.cg.shared.global [%0], [%1], 16;" :: "r"(dst), "l"(src) : "memory")
#define CP_COMMIT() asm volatile("cp.async.commit_group;" ::: "memory")
#define CP_WAIT(n)  asm volatile("cp.async.wait_group %0;" :: "n"(n) : "memory")

__device__ __forceinline__ void mma_f16(float* d, const uint32_t* a, const uint32_t* b) {
    asm volatile(
        "mma.sync.aligned.m16n8k16.row.col.f32.f16.f16.f32 "
        "{%0,%1,%2,%3}, {%4,%5,%6,%7}, {%8,%9}, {%0,%1,%2,%3};"
        : "+f"(d[0]), "+f"(d[1]), "+f"(d[2]), "+f"(d[3])
        : "r"(a[0]), "r"(a[1]), "r"(a[2]), "r"(a[3]), "r"(b[0]), "r"(b[1]));
}
__device__ __forceinline__ void ldsm_x4(uint32_t* r, uint32_t addr) {
    asm volatile("ldmatrix.sync.aligned.m8n8.x4.shared.b16 {%0,%1,%2,%3}, [%4];"
        : "=r"(r[0]), "=r"(r[1]), "=r"(r[2]), "=r"(r[3]) : "r"(addr));
}

// ---- packed fp32x2 ----
__device__ __forceinline__ u64 pack2(float lo, float hi) {
    u64 r; asm("mov.b64 %0, {%1,%2};" : "=l"(r) : "f"(lo), "f"(hi)); return r;
}
__device__ __forceinline__ float2 unpack2(u64 v) {
    float2 f; asm("mov.b64 {%0,%1}, %2;" : "=f"(f.x), "=f"(f.y) : "l"(v)); return f;
}
__device__ __forceinline__ u64 fma2(u64 a, u64 b, u64 c) {
    u64 d; asm("fma.rn.f32x2 %0, %1, %2, %3;" : "=l"(d) : "l"(a), "l"(b), "l"(c)); return d;
}
__device__ __forceinline__ u64 mul2(u64 a, u64 b) {
    u64 d; asm("mul.rn.f32x2 %0, %1, %2;" : "=l"(d) : "l"(a), "l"(b)); return d;
}
__device__ __forceinline__ void lds_v2u64(u64& a, u64& b, uint32_t addr) {
    asm volatile("ld.shared.v2.u64 {%0,%1}, [%2];" : "=l"(a), "=l"(b) : "r"(addr));
}

// ---------------- block reduction ----------------
__device__ __forceinline__ float blk_sum(float v, float* sb) {
    int lane = threadIdx.x & 31, wid = threadIdx.x >> 5;
    #pragma unroll
    for (int o = 16; o; o >>= 1) v += __shfl_down_sync(0xffffffffu, v, o);
    if (lane == 0) sb[wid] = v;
    __syncthreads();
    int nw = (blockDim.x + 31) >> 5;
    if (wid == 0) {
        float r = (lane < nw) ? sb[lane] : 0.f;
        #pragma unroll
        for (int o = 16; o; o >>= 1) r += __shfl_down_sync(0xffffffffu, r, o);
        if (lane == 0) sb[0] = r;
    }
    __syncthreads();
    float r = sb[0];
    __syncthreads();
    return r;
}

// ---------------- weight prep (MoE) ----------------
__global__ void transpose_half(const float* __restrict__ W, __half* __restrict__ Wh,
                               int K, int N)
{
    __shared__ float t[32][33];
    const int e = blockIdx.z;
    const int n0 = blockIdx.x * 32, k0 = blockIdx.y * 32;
    const float* We = W + (size_t)e * K * N;
    __half* Whe = Wh + (size_t)e * K * N;
    const int tx = threadIdx.x, ty = threadIdx.y;
    #pragma unroll
    for (int i = 0; i < 32; i += 8)
        t[ty + i][tx] = We[(size_t)(k0 + ty + i) * N + n0 + tx];
    __syncthreads();
    const int kk2 = (tx & 15) * 2;
    const int nn  = ty + ((tx >> 4) ? 8 : 0);
    #pragma unroll
    for (int i = 0; i < 32; i += 16) {
        int n = n0 + nn + i;
        __half2 v = __floats2half2_rn(t[kk2][nn + i], t[kk2 + 1][nn + i]);
        *(__half2*)&Whe[(size_t)n * K + k0 + kk2] = v;
    }
}

// ---------------- dense split-fp16 prep ----------------
__global__ void split_acts(const float* __restrict__ X, __half* __restrict__ Xs)
{
    size_t i = (size_t)blockIdx.x * blockDim.x + threadIdx.x;
    int m = (int)(i >> 9), kcol = (int)(i & 511);
    float v = X[i];
    __half hi = __float2half_rn(v);
    float lo = v - __half2float(hi);
    __half loh = __float2half_rn(lo);
    __half* row = Xs + (size_t)m*KP3;
    row[kcol] = hi; row[512 + kcol] = hi; row[1024 + kcol] = loh;
}

__global__ void split_wt(const float* __restrict__ W, __half* __restrict__ Ws)
{
    __shared__ float t[32][33];
    const int n0 = blockIdx.x * 32, k0 = blockIdx.y * 32;
    const int tx = threadIdx.x, ty = threadIdx.y;
    #pragma unroll
    for (int i = 0; i < 32; i += 8)
        t[ty + i][tx] = W[(size_t)(k0 + ty + i) * DM + n0 + tx];
    __syncthreads();
    #pragma unroll
    for (int i = 0; i < 32; i += 8) {
        float v = t[tx][ty + i];
        int n = n0 + ty + i, kk = k0 + tx;
        __half hi = __float2half_rn(v);
        float lo = v - __half2float(hi);
        __half* row = Ws + (size_t)n*KP3;
        row[kk] = hi;
        row[512 + kk] = __float2half_rn(lo);
        row[1024 + kk] = hi;
    }
}

// ---------------- HMMA tile constants (3-stage pipeline) ----------------
#define APH 40
#define BPH 40
#define ABUFH (128*APH)
#define BBUFH (256*BPH)
#define NSTG  3
#define HMMA_SMEM_BYTES (NSTG*(ABUFH + BBUFH) * 2)   // 92160

// ---------------- dense split-fp16 HMMA body ----------------
__device__ __forceinline__ void dense_hmma_body(
    __half* smh, const __half* __restrict__ Xs, const __half* __restrict__ Ws,
    float* __restrict__ C, const float* __restrict__ R, int epi, int bx, int mt)
{
    constexpr int NC = KP3 / 32;
    __half* Abuf = smh;
    __half* Bbuf = smh + NSTG*ABUFH;

    const int tid = threadIdx.x;
    const int wid = tid >> 5, lane = tid & 31;
    const int wm = wid & 1, wn = wid >> 1;
    const int m0w = wm*64, n0w = wn*64;
    const int r = lane >> 2, cq = lane & 3;
    const int n0 = bx * 256;

    const int rowA = tid >> 1, segA = tid & 1;
    const __half* srcA = Xs + (size_t)(mt*128 + rowA)*KP3 + segA*16;
    const uint32_t smA = smem_cast(Abuf) + (uint32_t)(rowA*APH + segA*16)*2;
    const __half* srcB = Ws + (size_t)(n0 + tid)*KP3;
    const uint32_t smB = smem_cast(Bbuf) + (uint32_t)(tid*BPH)*2;

    const uint32_t lmA = smem_cast(Abuf)
        + (uint32_t)(((m0w + (lane & 15))*APH + ((lane >> 4) & 1)*8) * 2);
    const uint32_t lmB = smem_cast(Bbuf)
        + (uint32_t)((((lane & 7) + ((lane >> 4) & 1)*8)*BPH + ((lane >> 3) & 1)*8) * 2);

    float acc[4][8][4];
    #pragma unroll
    for (int mi = 0; mi < 4; mi++)
        #pragma unroll
        for (int ni = 0; ni < 8; ni++)
            #pragma unroll
            for (int q = 0; q < 4; q++) acc[mi][ni][q] = 0.f;

    auto load_chunk = [&](int c) {
        uint32_t da = smA + (uint32_t)(c % NSTG)*(ABUFH*2);
        const __half* sa = srcA + c*32;
        CP_ASYNC16(da,      sa);
        CP_ASYNC16(da + 16, sa + 8);
        uint32_t db = smB + (uint32_t)(c % NSTG)*(BBUFH*2);
        const __half* sb2 = srcB + c*32;
        #pragma unroll
        for (int i = 0; i < 4; i++) CP_ASYNC16(db + i*16, sb2 + i*8);
        CP_COMMIT();
    };

    load_chunk(0);
    load_chunk(1);
    for (int c = 0; c < NC; c++) {
        if (c + 2 < NC)      { load_chunk(c + 2); CP_WAIT(2); }
        else if (c + 1 < NC) { CP_WAIT(1); }
        else                 { CP_WAIT(0); }
        __syncthreads();

        const uint32_t bufA = lmA + (uint32_t)(c % NSTG)*(ABUFH*2);
        const uint32_t bufB = lmB + (uint32_t)(c % NSTG)*(BBUFH*2);
        #pragma unroll
        for (int ks = 0; ks < 2; ks++) {
            uint32_t a[4][4];
            #pragma unroll
            for (int mi = 0; mi < 4; mi++)
                ldsm_x4(a[mi], bufA + (uint32_t)((mi*16*APH + ks*16)*2));
            uint32_t b[8][2];
            #pragma unroll
            for (int j = 0; j < 4; j++) {
                uint32_t rr[4];
                ldsm_x4(rr, bufB + (uint32_t)(((n0w + 16*j)*BPH + ks*16)*2));
                b[2*j  ][0] = rr[0]; b[2*j  ][1] = rr[1];
                b[2*j+1][0] = rr[2]; b[2*j+1][1] = rr[3];
            }
            #pragma unroll
            for (int mi = 0; mi < 4; mi++)
                #pragma unroll
                for (int ni = 0; ni < 8; ni++)
                    mma_f16(acc[mi][ni], a[mi], b[ni]);
        }
        __syncthreads();
    }

    #pragma unroll
    for (int mi = 0; mi < 4; mi++) {
        int mrow = mt*128 + m0w + mi*16 + r;
        float* C0 = C + (size_t)mrow*DM + n0 + n0w;
        float* C1 = C + (size_t)(mrow + 8)*DM + n0 + n0w;
        const float* R0 = epi ? (R + (size_t)mrow*DM + n0 + n0w) : (const float*)0;
        const float* R1 = epi ? (R + (size_t)(mrow + 8)*DM + n0 + n0w) : (const float*)0;
        #pragma unroll
        for (int ni = 0; ni < 8; ni++) {
            int col = ni*8 + 2*cq;
            float2 v0 = make_float2(acc[mi][ni][0], acc[mi][ni][1]);
            float2 v1 = make_float2(acc[mi][ni][2], acc[mi][ni][3]);
            if (epi) {
                float2 r0 = *(const float2*)(R0 + col);
                float2 r1 = *(const float2*)(R1 + col);
                v0.x = fmaxf(v0.x, 0.f) + r0.x; v0.y = fmaxf(v0.y, 0.f) + r0.y;
                v1.x = fmaxf(v1.x, 0.f) + r1.x; v1.y = fmaxf(v1.y, 0.f) + r1.y;
            }
            *(float2*)(C0 + col) = v0;
            *(float2*)(C1 + col) = v1;
        }
    }
}

__global__ __launch_bounds__(256)
void qkv_hmma(const __half* __restrict__ Xs,
              const __half* __restrict__ Wq, const __half* __restrict__ Wk, const __half* __restrict__ Wv,
              float* __restrict__ Cq, float* __restrict__ Ck, float* __restrict__ Cv)
{
    extern __shared__ __half smh[];
    const __half* W = (blockIdx.z == 0) ? Wq : (blockIdx.z == 1) ? Wk : Wv;
    float*        C = (blockIdx.z == 0) ? Cq : (blockIdx.z == 1) ? Ck : Cv;
    dense_hmma_body(smh, Xs, W, C, (const float*)0, 0, blockIdx.x, blockIdx.y);
}

__global__ __launch_bounds__(256)
void wo_hmma(const __half* __restrict__ Xs, const __half* __restrict__ W,
             float* __restrict__ C, const float* __restrict__ R)
{
    extern __shared__ __half smh[];
    dense_hmma_body(smh, Xs, W, C, R, 1, blockIdx.x, blockIdx.y);
}

// ---------------- MoE grouped GEMM (fp16 output, 3-stage) ----------------
template<int KDIM, int NDIM>
__global__ __launch_bounds__(256)
void moe_hmma(const __half* __restrict__ X, const int* __restrict__ rowmap,
              const __half* __restrict__ W, __half* __restrict__ C)
{
    constexpr int NC = KDIM / 32;
    extern __shared__ __half smh[];
    __half* Abuf = smh;
    __half* Bbuf = smh + NSTG*ABUFH;

    const int tid = threadIdx.x;
    const int wid = tid >> 5, lane = tid & 31;
    const int wm = wid & 1, wn = wid >> 1;
    const int m0w = wm*64, n0w = wn*64;
    const int r = lane >> 2, cq = lane & 3;

    const int e  = blockIdx.z;
    const int mt = blockIdx.y;
    const int n0 = blockIdx.x * 256;

    const int rowA = tid >> 1, segA = tid & 1;
    int token = rowmap[e*SLOTS + mt*128 + rowA];
    if (token < 0) token = 0;
    const __half* srcA = X + (size_t)token * KDIM + segA*16;
    const uint32_t smA = smem_cast(Abuf) + (uint32_t)(rowA*APH + segA*16)*2;

    const int rowB = tid;
    const __half* srcB = W + ((size_t)e*NDIM + n0 + rowB) * KDIM;
    const uint32_t smB = smem_cast(Bbuf) + (uint32_t)(rowB*BPH)*2;

    const uint32_t lmA = smem_cast(Abuf)
        + (uint32_t)(((m0w + (lane & 15))*APH + ((lane >> 4) & 1)*8) * 2);
    const uint32_t lmB = smem_cast(Bbuf)
        + (uint32_t)((((lane & 7) + ((lane >> 4) & 1)*8)*BPH + ((lane >> 3) & 1)*8) * 2);

    float acc[4][8][4];
    #pragma unroll
    for (int mi = 0; mi < 4; mi++)
        #pragma unroll
        for (int ni = 0; ni < 8; ni++)
            #pragma unroll
            for (int q = 0; q < 4; q++) acc[mi][ni][q] = 0.f;

    auto load_chunk = [&](int c) {
        uint32_t da = smA + (uint32_t)(c % NSTG)*(ABUFH*2);
        const __half* sa = srcA + c*32;
        CP_ASYNC16(da,      sa);
        CP_ASYNC16(da + 16, sa + 8);
        uint32_t db = smB + (uint32_t)(c % NSTG)*(BBUFH*2);
        const __half* sb2 = srcB + c*32;
        #pragma unroll
        for (int i = 0; i < 4; i++) CP_ASYNC16(db + i*16, sb2 + i*8);
        CP_COMMIT();
    };

    load_chunk(0);
    load_chunk(1);
    for (int c = 0; c < NC; c++) {
        if (c + 2 < NC)      { load_chunk(c + 2); CP_WAIT(2); }
        else if (c + 1 < NC) { CP_WAIT(1); }
        else                 { CP_WAIT(0); }
        __syncthreads();

        const uint32_t bufA = lmA + (uint32_t)(c % NSTG)*(ABUFH*2);
        const uint32_t bufB = lmB + (uint32_t)(c % NSTG)*(BBUFH*2);
        #pragma unroll
        for (int ks = 0; ks < 2; ks++) {
            uint32_t a[4][4];
            #pragma unroll
            for (int mi = 0; mi < 4; mi++)
                ldsm_x4(a[mi], bufA + (uint32_t)((mi*16*APH + ks*16)*2));
            uint32_t b[8][2];
            #pragma unroll
            for (int j = 0; j < 4; j++) {
                uint32_t rr[4];
                ldsm_x4(rr, bufB + (uint32_t)(((n0w + 16*j)*BPH + ks*16)*2));
                b[2*j  ][0] = rr[0]; b[2*j  ][1] = rr[1];
                b[2*j+1][0] = rr[2]; b[2*j+1][1] = rr[3];
            }
            #pragma unroll
            for (int mi = 0; mi < 4; mi++)
                #pragma unroll
                for (int ni = 0; ni < 8; ni++)
                    mma_f16(acc[mi][ni], a[mi], b[ni]);
        }
        __syncthreads();
    }

    #pragma unroll
    for (int mi = 0; mi < 4; mi++) {
        int mrow = mt*128 + m0w + mi*16 + r;
        __half* C0 = C + ((size_t)e*SLOTS + mrow    )*NDIM + n0 + n0w;
        __half* C1 = C + ((size_t)e*SLOTS + mrow + 8)*NDIM + n0 + n0w;
        #pragma unroll
        for (int ni = 0; ni < 8; ni++) {
            int col = ni*8 + 2*cq;
            *(__half2*)(C0 + col) = __floats2half2_rn(acc[mi][ni][0], acc[mi][ni][1]);
            *(__half2*)(C1 + col) = __floats2half2_rn(acc[mi][ni][2], acc[mi][ni][3]);
        }
    }
}

// ---------------- split-KV attention (1 thread/query) ----------------
__global__ __launch_bounds__(64)
void attn_split_kernel(const float* __restrict__ Q, const float* __restrict__ K,
                       const float* __restrict__ V,
                       float* __restrict__ opart, float* __restrict__ ml)
{
    __shared__ float Ks[2][32][64];
    __shared__ float Vs[2][32][64];
    const int bh = blockIdx.y;
    const int b = bh / NH, h = bh % NH;
    const int split = blockIdx.z;
    const int qi = blockIdx.x*64 + threadIdx.x;
    const int row = b*SEQ + qi;
    const size_t qoff = (size_t)row*DM + h*64;
    const size_t kbase = ((size_t)b*SEQ)*DM + h*64;

    const uint32_t sK = smem_cast(Ks);
    const uint32_t sV = smem_cast(Vs);

    u64 q2[32];
    #pragma unroll
    for (int d = 0; d < 64; d += 4) {
        float4 t = *(const float4*)&Q[qoff + d];
        q2[d/2]   = pack2(t.x*0.125f, t.y*0.125f);
        q2[d/2+1] = pack2(t.z*0.125f, t.w*0.125f);
    }
    float m = -1e30f, l = 0.f;
    u64 o2[32];
    #pragma unroll
    for (int d2 = 0; d2 < 32; d2++) o2[d2] = 0ull;

    auto load_tile = [&](int kt, int buf) {
        #pragma unroll
        for (int it = 0; it < 8; it++) {
            int f = threadIdx.x + it*64;
            int j = f >> 4; int d4 = (f & 15)*4;
            uint32_t off = (uint32_t)(buf*8192 + (j*64 + d4)*4);
            size_t src = kbase + (size_t)(kt + j)*DM + d4;
            CP_ASYNC16(sK + off, &K[src]);
            CP_ASYNC16(sV + off, &V[src]);
        }
        CP_COMMIT();
    };

    const int t0 = split * 8;
    load_tile(t0*32, 0);
    for (int t = 0; t < 8; t++) {
        const int buf = t & 1;
        if (t + 1 < 8) { load_tile((t0 + t + 1)*32, (t+1) & 1); CP_WAIT(1); }
        else           { CP_WAIT(0); }
        __syncthreads();

        float s[32];
        #pragma unroll
        for (int j = 0; j < 32; j++) {
            const uint32_t kj = sK + (uint32_t)(buf*8192 + j*256);
            u64 accA = 0ull, accB = 0ull;
            #pragma unroll
            for (int g = 0; g < 16; g++) {
                u64 x, y;
                lds_v2u64(x, y, kj + (uint32_t)(g*16));
                accA = fma2(q2[2*g],   x, accA);
                accB = fma2(q2[2*g+1], y, accB);
            }
            float2 fa = unpack2(accA), fb = unpack2(accB);
            s[j] = (fa.x + fa.y) + (fb.x + fb.y);
        }
        float tmax = m;
        #pragma unroll
        for (int j = 0; j < 32; j++) tmax = fmaxf(tmax, s[j]);
        float f = __expf(m - tmax);
        l *= f;
        u64 f2 = pack2(f, f);
        #pragma unroll
        for (int d2 = 0; d2 < 32; d2++) o2[d2] = mul2(o2[d2], f2);
        #pragma unroll
        for (int j = 0; j < 32; j++) {
            float p = __expf(s[j] - tmax);
            l += p;
            u64 p2v = pack2(p, p);
            const uint32_t vj = sV + (uint32_t)(buf*8192 + j*256);
            #pragma unroll
            for (int g = 0; g < 16; g++) {
                u64 x, y;
                lds_v2u64(x, y, vj + (uint32_t)(g*16));
                o2[2*g]   = fma2(p2v, x, o2[2*g]);
                o2[2*g+1] = fma2(p2v, y, o2[2*g+1]);
            }
        }
        m = tmax;
        __syncthreads();
    }
    float* op = opart + (size_t)split*NROWS*DM + qoff;
    #pragma unroll
    for (int d2 = 0; d2 < 32; d2 += 2) {
        float2 pa = unpack2(o2[d2]), pb = unpack2(o2[d2+1]);
        *(float4*)&op[d2*2] = make_float4(pa.x, pa.y, pb.x, pb.y);
    }
    float* mlp = ml + (((size_t)split*NROWS + row)*NH + h)*2;
    mlp[0] = m; mlp[1] = l;
}

// merge -> ctx split only (dead fp32 ctx store removed)
__global__ __launch_bounds__(512)
void attn_merge_kernel(const float* __restrict__ opart, const float* __restrict__ ml,
                       __half* __restrict__ Cs)
{
    const int row = blockIdx.x;
    const int d = threadIdx.x;
    const int h = d >> 6;
    float mm[NSPLIT], llv[NSPLIT];
    float M = -1e30f;
    #pragma unroll
    for (int s = 0; s < NSPLIT; s++) {
        const float* mlp = ml + (((size_t)s*NROWS + row)*NH + h)*2;
        mm[s] = mlp[0]; llv[s] = mlp[1];
        M = fmaxf(M, mm[s]);
    }
    float denom = 0.f, acc = 0.f;
    #pragma unroll
    for (int s = 0; s < NSPLIT; s++) {
        float sc = __expf(mm[s] - M);
        denom += llv[s] * sc;
        acc   += sc * opart[(size_t)s*NROWS*DM + (size_t)row*DM + d];
    }
    float v = acc / denom;
    __half hi = __float2half_rn(v);
    float lo = v - __half2float(hi);
    __half* cr = Cs + (size_t)row*KP3;
    cr[d] = hi; cr[512 + d] = hi; cr[1024 + d] = __float2half_rn(lo);
}

// ---------------- layernorm ----------------
__global__ void ln_kernel(const float* __restrict__ X, float* __restrict__ Y,
                          __half* __restrict__ Yh,
                          const float* __restrict__ gg, const float* __restrict__ bb, int len)
{
    __shared__ float sb[32];
    const int row = blockIdx.x;
    const float* xr = X + (size_t)row*len;
    float sum = 0.f;
    for (int c = threadIdx.x; c < len; c += blockDim.x) sum += xr[c];
    float mean = blk_sum(sum, sb) / len;
    float s2 = 0.f;
    for (int c = threadIdx.x; c < len; c += blockDim.x) { float d = xr[c]-mean; s2 += d*d; }
    float var = blk_sum(s2, sb) / len;
    float r = rsqrtf(var + EPSV);
    for (int c = threadIdx.x; c < len; c += blockDim.x) {
        float v = (xr[c]-mean)*r*gg[c] + bb[c];
        Y[(size_t)row*len + c] = v;
        if (Yh) Yh[(size_t)row*len + c] = __float2half_rn(v);
    }
}

// ---------------- gating (fp32 exact — unchanged) ----------------
__global__ void gate_kernel(const float* __restrict__ Xres, const float* __restrict__ wg)
{
    __shared__ float xr[DM];
    __shared__ float lg[NE];
    const int tt = blockIdx.x;
    const int grp = tt >> 11, ti = tt & 2047;
    const int row = ((ti >> 8) * SEQ) + grp*256 + (ti & 255);
    for (int c = threadIdx.x; c < DM; c += blockDim.x) xr[c] = Xres[(size_t)row*DM + c];
    __syncthreads();
    if (threadIdx.x < NE) {
        float acc = 0.f;
        #pragma unroll 8
        for (int d = 0; d < DM; d++) acc = fmaf(xr[d], wg[d*NE + threadIdx.x], acc);
        lg[threadIdx.x] = acc;
    }
    __syncthreads();
    if (threadIdx.x == 0) {
        int i1 = 0; float v1 = lg[0];
        for (int e2 = 1; e2 < NE; e2++) if (lg[e2] > v1) { v1 = lg[e2]; i1 = e2; }
        int i2 = -1; float v2 = -1e30f;
        for (int e2 = 0; e2 < NE; e2++) if (e2 != i1 && lg[e2] > v2) { v2 = lg[e2]; i2 = e2; }
        float r2 = expf(v2 - v1);
        float inv = 1.f / (1.f + r2);
        g_e1[tt] = i1; g_e2[tt] = i2;
        g_wa[tt] = inv; g_wb[tt] = r2 * inv;
    }
}

// ---------------- GShard slot assignment ----------------
__global__ void assign_kernel()
{
    __shared__ int scnt[NE];
    const int grp = blockIdx.x;
    const int tid = threadIdx.x, lane = tid & 31, e = tid >> 5;
    for (int i = tid; i < NE*GOFF; i += blockDim.x) {
        int ee = i / GOFF, s = i % GOFF;
        g_rowg[ee*SLOTS + grp*GOFF + s] = -1;
        g_rowl[ee*SLOTS + grp*GOFF + s] = -1;
    }
    __syncthreads();
    int cnt = 0;
    for (int base = 0; base < TG; base += 32) {
        int ti = base + lane;
        int tt = grp*TG + ti;
        bool mm = (g_e1[tt] == e);
        unsigned bal = __ballot_sync(0xffffffffu, mm);
        if (mm) {
            int loc = cnt + __popc(bal & ((1u << lane) - 1u));
            if (loc < CAP) {
                int srow = grp*GOFF + loc;
                g_s1[tt] = srow;
                int row = ((ti >> 8) * SEQ) + grp*256 + (ti & 255);
                g_rowg[e*SLOTS + srow] = row;
                g_rowl[e*SLOTS + srow] = tt;
            } else g_s1[tt] = -1;
        }
        cnt += __popc(bal);
    }
    if (lane == 0) scnt[e] = cnt;
    __syncthreads();
    cnt = scnt[e];
    for (int base = 0; base < TG; base += 32) {
        int ti = base + lane;
        int tt = grp*TG + ti;
        bool mm = (g_e2[tt] == e);
        unsigned bal = __ballot_sync(0xffffffffu, mm);
        if (mm) {
            int loc = cnt + __popc(bal & ((1u << lane) - 1u));
            if (loc < CAP) {
                int srow = grp*GOFF + loc;
                g_s2[tt] = srow;
                int row = ((ti >> 8) * SEQ) + grp*256 + (ti & 255);
                g_rowg[e*SLOTS + srow] = row;
                g_rowl[e*SLOTS + srow] = tt;
            } else g_s2[tt] = -1;
        }
        cnt += __popc(bal);
    }
}

// ---------------- combine MoE1 (fp16 slots) + bias + LN + relu -> fp16 ----------------
__global__ void combine1_kernel(const float* __restrict__ b1)
{
    __shared__ float sb[32];
    const int tt = blockIdx.x;
    const int grp = tt >> 11;
    const float* lng = g_lnp[2*grp];
    const float* lnb = g_lnp[2*grp+1];
    const int e1 = g_e1[tt], e2 = g_e2[tt], s1 = g_s1[tt], s2 = g_s2[tt];
    const float wa = g_wa[tt], wb = g_wb[tt];
    const __half* p1 = (s1 >= 0) ? &g_sloth[((size_t)e1*SLOTS + s1)*DI] : (const __half*)0;
    const __half* p2 = (s2 >= 0) ? &g_sloth[((size_t)e2*SLOTS + s2)*DI] : (const __half*)0;
    float vals[8];
    float sum = 0.f;
    #pragma unroll
    for (int i = 0; i < 8; i++) {
        int c = threadIdx.x + i*256;
        float hv = 0.f;
        if (p1) hv += wa * (__half2float(p1[c]) + b1[e1*DI + c]);
        if (p2) hv += wb * (__half2float(p2[c]) + b1[e2*DI + c]);
        vals[i] = hv; sum += hv;
    }
    float mean = blk_sum(sum, sb) / DI;
    float s2s = 0.f;
    #pragma unroll
    for (int i = 0; i < 8; i++) { float d = vals[i]-mean; s2s += d*d; }
    float var = blk_sum(s2s, sb) / DI;
    float r = rsqrtf(var + EPSV);
    #pragma unroll
    for (int i = 0; i < 8; i++) {
        int c = threadIdx.x + i*256;
        float v = fmaxf((vals[i]-mean)*r*lng[c] + lnb[c], 0.f);
        g_hpost[(size_t)tt*DI + c] = __float2half_rn(v);
    }
}

// ---------------- combine MoE2 (fp16 slots) + bias + residual + FINAL LN ----------------
__global__ void combine2_ln_kernel(const float* __restrict__ b2, float* __restrict__ out,
                                   const float* __restrict__ gg, const float* __restrict__ bb)
{
    __shared__ float sb[32];
    const int tt = blockIdx.x;
    const int grp = tt >> 11, ti = tt & 2047;
    const int e1 = g_e1[tt], e2 = g_e2[tt], s1 = g_s1[tt], s2 = g_s2[tt];
    const float wa = g_wa[tt], wb = g_wb[tt];
    const int row = ((ti >> 8) * SEQ) + grp*256 + (ti & 255);
    float vals[4];
    float sum = 0.f;
    #pragma unroll
    for (int i = 0; i < 4; i++) {
        int c = threadIdx.x + i*128;
        float y = 0.f;
        if (s1 >= 0) y += wa * (__half2float(g_sloty[((size_t)e1*SLOTS + s1)*DM + c]) + b2[e1*DM + c]);
        if (s2 >= 0) y += wb * (__half2float(g_sloty[((size_t)e2*SLOTS + s2)*DM + c]) + b2[e2*DM + c]);
        y += g_res[(size_t)row*DM + c];
        vals[i] = y; sum += y;
    }
    float mean = blk_sum(sum, sb) / DM;
    float s2s = 0.f;
    #pragma unroll
    for (int i = 0; i < 4; i++) { float d = vals[i]-mean; s2s += d*d; }
    float var = blk_sum(s2s, sb) / DM;
    float r = rsqrtf(var + EPSV);
    #pragma unroll
    for (int i = 0; i < 4; i++) {
        int c = threadIdx.x + i*128;
        out[(size_t)row*DM + c] = (vals[i]-mean)*r*gg[c] + bb[c];
    }
}

__global__ void set_lnp_kernel(const float* a0, const float* a1, const float* a2, const float* a3,
                               const float* a4, const float* a5, const float* a6, const float* a7)
{
    g_lnp[0]=a0; g_lnp[1]=a1; g_lnp[2]=a2; g_lnp[3]=a3;
    g_lnp[4]=a4; g_lnp[5]=a5; g_lnp[6]=a6; g_lnp[7]=a7;
}

// ---------------- launch ----------------
extern "C" void kernel_launch(void* const* d_in, const int* in_sizes, int n_in,
                              void* d_out, int out_size)
{
    const float *x=0,*wq=0,*wk=0,*wv=0,*wo=0,*ln_attn_g=0,*ln_attn_b=0,*wg1=0,*w1=0,*b1=0,
                *w2=0,*b2=0,*ln_out_g=0,*ln_out_b=0;
    const float* ln2048[8] = {0,0,0,0,0,0,0,0};
    int c262=0,c512=0,c12k=0,c25m=0,c49k=0,c2k=0;
    for (int i = 0; i < n_in; i++) {
        const float* p = (const float*)d_in[i];
        switch (in_sizes[i]) {
            case 4194304: x = p; break;
            case 262144:
                if (c262==0) wq=p; else if (c262==1) wk=p; else if (c262==2) wv=p; else wo=p;
                c262++; break;
            case 512:
                if (c512==0) ln_attn_g=p; else if (c512==1) ln_attn_b=p;
                else if (c512==2) ln_out_g=p; else ln_out_b=p;
                c512++; break;
            case 12288:
                if (c12k==0) wg1=p; else b2=p;
                c12k++; break;
            case 25165824:
                if (c25m==0) w1=p; else w2=p;
                c25m++; break;
            case 49152:
                if (c49k==0) b1=p;
                c49k++; break;
            case 2048:
                if (c2k < 8) ln2048[c2k] = p;
                c2k++; break;
            default: break;
        }
    }

    float *p_q,*p_k,*p_v,*p_tmp,*p_res,*p_part,*p_ml;
    __half *p_resh,*p_xs,*p_cs,*p_wqs,*p_wks,*p_wvs,*p_wos,*p_wh1,*p_wh2,*p_sloth,*p_sloty,*p_hpost;
    int *p_rowg,*p_rowl;
    cudaGetSymbolAddress((void**)&p_q,     g_q);
    cudaGetSymbolAddress((void**)&p_k,     g_k);
    cudaGetSymbolAddress((void**)&p_v,     g_v);
    cudaGetSymbolAddress((void**)&p_tmp,   g_tmp);
    cudaGetSymbolAddress((void**)&p_res,   g_res);
    cudaGetSymbolAddress((void**)&p_resh,  g_resh);
    cudaGetSymbolAddress((void**)&p_part,  g_part);
    cudaGetSymbolAddress((void**)&p_ml,    g_ml);
    cudaGetSymbolAddress((void**)&p_xs,    g_xs);
    cudaGetSymbolAddress((void**)&p_cs,    g_cs);
    cudaGetSymbolAddress((void**)&p_wqs,   g_wqs);
    cudaGetSymbolAddress((void**)&p_wks,   g_wks);
    cudaGetSymbolAddress((void**)&p_wvs,   g_wvs);
    cudaGetSymbolAddress((void**)&p_wos,   g_wos);
    cudaGetSymbolAddress((void**)&p_wh1,   g_wh1);
    cudaGetSymbolAddress((void**)&p_wh2,   g_wh2);
    cudaGetSymbolAddress((void**)&p_sloth, g_sloth);
    cudaGetSymbolAddress((void**)&p_sloty, g_sloty);
    cudaGetSymbolAddress((void**)&p_hpost, g_hpost);
    cudaGetSymbolAddress((void**)&p_rowg,  g_rowg);
    cudaGetSymbolAddress((void**)&p_rowl,  g_rowl);

    float* out = (float*)d_out;

    cudaFuncSetAttribute(moe_hmma<DM, DI>, cudaFuncAttributeMaxDynamicSharedMemorySize, HMMA_SMEM_BYTES);
    cudaFuncSetAttribute(moe_hmma<DI, DM>, cudaFuncAttributeMaxDynamicSharedMemorySize, HMMA_SMEM_BYTES);
    cudaFuncSetAttribute(qkv_hmma, cudaFuncAttributeMaxDynamicSharedMemorySize, HMMA_SMEM_BYTES);
    cudaFuncSetAttribute(wo_hmma,  cudaFuncAttributeMaxDynamicSharedMemorySize, HMMA_SMEM_BYTES);

    static cudaStream_t s2 = 0;
    static cudaEvent_t evFork = 0, evJoin = 0;
    if (!s2) {
        cudaStreamCreateWithFlags(&s2, cudaStreamNonBlocking);
        cudaEventCreateWithFlags(&evFork, cudaEventDisableTiming);
        cudaEventCreateWithFlags(&evJoin, cudaEventDisableTiming);
    }

    // 0a) fork: MoE weight transposes on side stream
    cudaEventRecord(evFork, 0);
    cudaStreamWaitEvent(s2, evFork, 0);
    transpose_half<<<dim3(DI/32, DM/32, NE), dim3(32,8), 0, s2>>>(w1, p_wh1, DM, DI);
    transpose_half<<<dim3(DM/32, DI/32, NE), dim3(32,8), 0, s2>>>(w2, p_wh2, DI, DM);
    cudaEventRecord(evJoin, s2);

    // 0b) main-stream prep
    split_wt<<<dim3(16,16), dim3(32,8)>>>(wq, p_wqs);
    split_wt<<<dim3(16,16), dim3(32,8)>>>(wk, p_wks);
    split_wt<<<dim3(16,16), dim3(32,8)>>>(wv, p_wvs);
    split_wt<<<dim3(16,16), dim3(32,8)>>>(wo, p_wos);
    split_acts<<<(NROWS*DM)/256, 256>>>(x, p_xs);
    set_lnp_kernel<<<1,1>>>(ln2048[0],ln2048[1],ln2048[2],ln2048[3],
                            ln2048[4],ln2048[5],ln2048[6],ln2048[7]);

    // 1) QKV projections
    qkv_hmma<<<dim3(DM/256, NROWS/128, 3), 256, HMMA_SMEM_BYTES>>>(
        p_xs, p_wqs, p_wks, p_wvs, p_q, p_k, p_v);

    // 2) attention: split-KV x4 + merge (emits ctx split only)
    attn_split_kernel<<<dim3(SEQ/64, NB*NH, NSPLIT), 64>>>(p_q, p_k, p_v, p_part, p_ml);
    attn_merge_kernel<<<NROWS, 512>>>(p_part, p_ml, p_cs);

    // 3) output projection + LN
    wo_hmma<<<dim3(DM/256, NROWS/128), 256, HMMA_SMEM_BYTES>>>(p_cs, p_wos, p_tmp, x);
    ln_kernel<<<NROWS, 256>>>(p_tmp, p_res, p_resh, ln_attn_g, ln_attn_b, DM);

    // 4) routing
    gate_kernel<<<NTOK, 128>>>(p_res, wg1);
    assign_kernel<<<NGRP, NE*32>>>();

    // join side stream before MoE consumes transposed weights
    cudaStreamWaitEvent(0, evJoin, 0);

    // 5) MoE (fp16 slot buffers)
    moe_hmma<DM, DI><<<dim3(DI/256, SLOTS/128, NE), 256, HMMA_SMEM_BYTES>>>(p_resh, p_rowg, p_wh1, p_sloth);
    combine1_kernel<<<NTOK, 256>>>(b1);
    moe_hmma<DI, DM><<<dim3(DM/256, SLOTS/128, NE), 256, HMMA_SMEM_BYTES>>>(p_hpost, p_rowl, p_wh2, p_sloty);
    combine2_ln_kernel<<<NTOK, 128>>>(b2, out, ln_out_g, ln_out_b);

    (void)out_size;
}

// round 17
// speedup vs baseline: 1.0180x; 1.0180x over previous
#include <cuda_runtime.h>
#include <cuda_fp16.h>
#include <cstdint>
#include <cstddef>

// ---------------- problem constants ----------------
#define NB    8
#define SEQ   1024
#define DM    512
#define NH    8
#define DI    2048
#define NE    24
#define CAP   171
#define TG    2048
#define NGRP  4
#define NROWS (NB*SEQ)      // 8192
#define NTOK  (NGRP*TG)     // 8192
#define SLOTS 768
#define GOFF  192
#define EPSV  1e-6f
#define NSPLIT 4
#define KP3   1536

typedef unsigned long long u64;

// ---------------- device scratch ----------------
__device__ float  g_q[NROWS*DM];
__device__ float  g_k[NROWS*DM];
__device__ float  g_v[NROWS*DM];
__device__ float  g_tmp[NROWS*DM];
__device__ float  g_res[NROWS*DM];
__device__ __half g_resh[NROWS*DM];
__device__ float  g_part[(size_t)NSPLIT*NROWS*DM];
__device__ float  g_ml[(size_t)NSPLIT*NROWS*NH*2];
__device__ __half g_xs[(size_t)NROWS*KP3];
__device__ __half g_cs[(size_t)NROWS*KP3];
__device__ __half g_wqs[(size_t)DM*KP3];
__device__ __half g_wks[(size_t)DM*KP3];
__device__ __half g_wvs[(size_t)DM*KP3];
__device__ __half g_wos[(size_t)DM*KP3];
__device__ __half g_wh1[(size_t)NE*DI*DM];
__device__ __half g_wh2[(size_t)NE*DM*DI];
__device__ __half g_sloth[(size_t)NE*SLOTS*DI];
__device__ __half g_sloty[(size_t)NE*SLOTS*DM];
__device__ __half g_hpost[(size_t)NTOK*DI];
__device__ int    g_e1[NTOK], g_e2[NTOK], g_s1[NTOK], g_s2[NTOK];
__device__ float  g_wa[NTOK], g_wb[NTOK];
__device__ int    g_rowg[NE*SLOTS];
__device__ int    g_rowl[NE*SLOTS];
__device__ const float* g_lnp[8];

// ---------------- PTX helpers ----------------
__device__ __forceinline__ uint32_t smem_cast(const void* p) {
    uint32_t a;
    asm("{ .reg .u64 t; cvta.to.shared.u64 t, %1; cvt.u32.u64 %0, t; }" : "=r"(a) : "l"(p));
    return a;
}
#define CP_ASYNC16(dst, src) \
    asm volatile("cp.async.cg.shared.global [%0], [%1], 16;" :: "r"(dst), "l"(src) : "memory")
#define CP_COMMIT() asm volatile("cp.async.commit_group;" ::: "memory")
#define CP_WAIT(n)  asm volatile("cp.async.wait_group %0;" :: "n"(n) : "memory")

__device__ __forceinline__ void mma_f16(float* d, const uint32_t* a, const uint32_t* b) {
    asm volatile(
        "mma.sync.aligned.m16n8k16.row.col.f32.f16.f16.f32 "
        "{%0,%1,%2,%3}, {%4,%5,%6,%7}, {%8,%9}, {%0,%1,%2,%3};"
        : "+f"(d[0]), "+f"(d[1]), "+f"(d[2]), "+f"(d[3])
        : "r"(a[0]), "r"(a[1]), "r"(a[2]), "r"(a[3]), "r"(b[0]), "r"(b[1]));
}
__device__ __forceinline__ void ldsm_x4(uint32_t* r, uint32_t addr) {
    asm volatile("ldmatrix.sync.aligned.m8n8.x4.shared.b16 {%0,%1,%2,%3}, [%4];"
        : "=r"(r[0]), "=r"(r[1]), "=r"(r[2]), "=r"(r[3]) : "r"(addr));
}

// ---- packed fp32x2 ----
__device__ __forceinline__ u64 pack2(float lo, float hi) {
    u64 r; asm("mov.b64 %0, {%1,%2};" : "=l"(r) : "f"(lo), "f"(hi)); return r;
}
__device__ __forceinline__ float2 unpack2(u64 v) {
    float2 f; asm("mov.b64 {%0,%1}, %2;" : "=f"(f.x), "=f"(f.y) : "l"(v)); return f;
}
__device__ __forceinline__ u64 fma2(u64 a, u64 b, u64 c) {
    u64 d; asm("fma.rn.f32x2 %0, %1, %2, %3;" : "=l"(d) : "l"(a), "l"(b), "l"(c)); return d;
}
__device__ __forceinline__ u64 mul2(u64 a, u64 b) {
    u64 d; asm("mul.rn.f32x2 %0, %1, %2;" : "=l"(d) : "l"(a), "l"(b)); return d;
}
__device__ __forceinline__ void lds_v2u64(u64& a, u64& b, uint32_t addr) {
    asm volatile("ld.shared.v2.u64 {%0,%1}, [%2];" : "=l"(a), "=l"(b) : "r"(addr));
}

// ---------------- block reduction ----------------
__device__ __forceinline__ float blk_sum(float v, float* sb) {
    int lane = threadIdx.x & 31, wid = threadIdx.x >> 5;
    #pragma unroll
    for (int o = 16; o; o >>= 1) v += __shfl_down_sync(0xffffffffu, v, o);
    if (lane == 0) sb[wid] = v;
    __syncthreads();
    int nw = (blockDim.x + 31) >> 5;
    if (wid == 0) {
        float r = (lane < nw) ? sb[lane] : 0.f;
        #pragma unroll
        for (int o = 16; o; o >>= 1) r += __shfl_down_sync(0xffffffffu, r, o);
        if (lane == 0) sb[0] = r;
    }
    __syncthreads();
    float r = sb[0];
    __syncthreads();
    return r;
}

// ---------------- weight prep (MoE) ----------------
__global__ void transpose_half(const float* __restrict__ W, __half* __restrict__ Wh,
                               int K, int N)
{
    __shared__ float t[32][33];
    const int e = blockIdx.z;
    const int n0 = blockIdx.x * 32, k0 = blockIdx.y * 32;
    const float* We = W + (size_t)e * K * N;
    __half* Whe = Wh + (size_t)e * K * N;
    const int tx = threadIdx.x, ty = threadIdx.y;
    #pragma unroll
    for (int i = 0; i < 32; i += 8)
        t[ty + i][tx] = We[(size_t)(k0 + ty + i) * N + n0 + tx];
    __syncthreads();
    const int kk2 = (tx & 15) * 2;
    const int nn  = ty + ((tx >> 4) ? 8 : 0);
    #pragma unroll
    for (int i = 0; i < 32; i += 16) {
        int n = n0 + nn + i;
        __half2 v = __floats2half2_rn(t[kk2][nn + i], t[kk2 + 1][nn + i]);
        *(__half2*)&Whe[(size_t)n * K + k0 + kk2] = v;
    }
}

// ---------------- dense split-fp16 prep ----------------
__global__ void split_acts(const float* __restrict__ X, __half* __restrict__ Xs)
{
    size_t i = (size_t)blockIdx.x * blockDim.x + threadIdx.x;
    int m = (int)(i >> 9), kcol = (int)(i & 511);
    float v = X[i];
    __half hi = __float2half_rn(v);
    float lo = v - __half2float(hi);
    __half loh = __float2half_rn(lo);
    __half* row = Xs + (size_t)m*KP3;
    row[kcol] = hi; row[512 + kcol] = hi; row[1024 + kcol] = loh;
}

__global__ void split_wt(const float* __restrict__ W, __half* __restrict__ Ws)
{
    __shared__ float t[32][33];
    const int n0 = blockIdx.x * 32, k0 = blockIdx.y * 32;
    const int tx = threadIdx.x, ty = threadIdx.y;
    #pragma unroll
    for (int i = 0; i < 32; i += 8)
        t[ty + i][tx] = W[(size_t)(k0 + ty + i) * DM + n0 + tx];
    __syncthreads();
    #pragma unroll
    for (int i = 0; i < 32; i += 8) {
        float v = t[tx][ty + i];
        int n = n0 + ty + i, kk = k0 + tx;
        __half hi = __float2half_rn(v);
        float lo = v - __half2float(hi);
        __half* row = Ws + (size_t)n*KP3;
        row[kk] = hi;
        row[512 + kk] = __float2half_rn(lo);
        row[1024 + kk] = hi;
    }
}

// ---------------- HMMA tile constants (2-stage pipeline, measured best) ----------------
#define APH 40
#define BPH 40
#define ABUFH (128*APH)
#define BBUFH (256*BPH)
#define HMMA_SMEM_BYTES ((2*ABUFH + 2*BBUFH) * 2)   // 61440

// ---------------- dense split-fp16 HMMA body ----------------
__device__ __forceinline__ void dense_hmma_body(
    __half* smh, const __half* __restrict__ Xs, const __half* __restrict__ Ws,
    float* __restrict__ C, const float* __restrict__ R, int epi, int bx, int mt)
{
    constexpr int NC = KP3 / 32;
    __half* Abuf = smh;
    __half* Bbuf = smh + 2*ABUFH;

    const int tid = threadIdx.x;
    const int wid = tid >> 5, lane = tid & 31;
    const int wm = wid & 1, wn = wid >> 1;
    const int m0w = wm*64, n0w = wn*64;
    const int r = lane >> 2, cq = lane & 3;
    const int n0 = bx * 256;

    const int rowA = tid >> 1, segA = tid & 1;
    const __half* srcA = Xs + (size_t)(mt*128 + rowA)*KP3 + segA*16;
    const uint32_t smA = smem_cast(Abuf) + (uint32_t)(rowA*APH + segA*16)*2;
    const __half* srcB = Ws + (size_t)(n0 + tid)*KP3;
    const uint32_t smB = smem_cast(Bbuf) + (uint32_t)(tid*BPH)*2;

    const uint32_t lmA = smem_cast(Abuf)
        + (uint32_t)(((m0w + (lane & 15))*APH + ((lane >> 4) & 1)*8) * 2);
    const uint32_t lmB = smem_cast(Bbuf)
        + (uint32_t)((((lane & 7) + ((lane >> 4) & 1)*8)*BPH + ((lane >> 3) & 1)*8) * 2);

    float acc[4][8][4];
    #pragma unroll
    for (int mi = 0; mi < 4; mi++)
        #pragma unroll
        for (int ni = 0; ni < 8; ni++)
            #pragma unroll
            for (int q = 0; q < 4; q++) acc[mi][ni][q] = 0.f;

    auto load_chunk = [&](int c) {
        uint32_t da = smA + (uint32_t)(c & 1)*(ABUFH*2);
        const __half* sa = srcA + c*32;
        CP_ASYNC16(da,      sa);
        CP_ASYNC16(da + 16, sa + 8);
        uint32_t db = smB + (uint32_t)(c & 1)*(BBUFH*2);
        const __half* sb2 = srcB + c*32;
        #pragma unroll
        for (int i = 0; i < 4; i++) CP_ASYNC16(db + i*16, sb2 + i*8);
        CP_COMMIT();
    };

    load_chunk(0);
    for (int c = 0; c < NC; c++) {
        if (c + 1 < NC) { load_chunk(c + 1); CP_WAIT(1); }
        else           { CP_WAIT(0); }
        __syncthreads();

        const uint32_t bufA = lmA + (uint32_t)(c & 1)*(ABUFH*2);
        const uint32_t bufB = lmB + (uint32_t)(c & 1)*(BBUFH*2);
        #pragma unroll
        for (int ks = 0; ks < 2; ks++) {
            uint32_t a[4][4];
            #pragma unroll
            for (int mi = 0; mi < 4; mi++)
                ldsm_x4(a[mi], bufA + (uint32_t)((mi*16*APH + ks*16)*2));
            uint32_t b[8][2];
            #pragma unroll
            for (int j = 0; j < 4; j++) {
                uint32_t rr[4];
                ldsm_x4(rr, bufB + (uint32_t)(((n0w + 16*j)*BPH + ks*16)*2));
                b[2*j  ][0] = rr[0]; b[2*j  ][1] = rr[1];
                b[2*j+1][0] = rr[2]; b[2*j+1][1] = rr[3];
            }
            #pragma unroll
            for (int mi = 0; mi < 4; mi++)
                #pragma unroll
                for (int ni = 0; ni < 8; ni++)
                    mma_f16(acc[mi][ni], a[mi], b[ni]);
        }
        __syncthreads();
    }

    #pragma unroll
    for (int mi = 0; mi < 4; mi++) {
        int mrow = mt*128 + m0w + mi*16 + r;
        float* C0 = C + (size_t)mrow*DM + n0 + n0w;
        float* C1 = C + (size_t)(mrow + 8)*DM + n0 + n0w;
        const float* R0 = epi ? (R + (size_t)mrow*DM + n0 + n0w) : (const float*)0;
        const float* R1 = epi ? (R + (size_t)(mrow + 8)*DM + n0 + n0w) : (const float*)0;
        #pragma unroll
        for (int ni = 0; ni < 8; ni++) {
            int col = ni*8 + 2*cq;
            float2 v0 = make_float2(acc[mi][ni][0], acc[mi][ni][1]);
            float2 v1 = make_float2(acc[mi][ni][2], acc[mi][ni][3]);
            if (epi) {
                float2 r0 = *(const float2*)(R0 + col);
                float2 r1 = *(const float2*)(R1 + col);
                v0.x = fmaxf(v0.x, 0.f) + r0.x; v0.y = fmaxf(v0.y, 0.f) + r0.y;
                v1.x = fmaxf(v1.x, 0.f) + r1.x; v1.y = fmaxf(v1.y, 0.f) + r1.y;
            }
            *(float2*)(C0 + col) = v0;
            *(float2*)(C1 + col) = v1;
        }
    }
}

__global__ __launch_bounds__(256)
void qkv_hmma(const __half* __restrict__ Xs,
              const __half* __restrict__ Wq, const __half* __restrict__ Wk, const __half* __restrict__ Wv,
              float* __restrict__ Cq, float* __restrict__ Ck, float* __restrict__ Cv)
{
    extern __shared__ __half smh[];
    const __half* W = (blockIdx.z == 0) ? Wq : (blockIdx.z == 1) ? Wk : Wv;
    float*        C = (blockIdx.z == 0) ? Cq : (blockIdx.z == 1) ? Ck : Cv;
    dense_hmma_body(smh, Xs, W, C, (const float*)0, 0, blockIdx.x, blockIdx.y);
}

__global__ __launch_bounds__(256)
void wo_hmma(const __half* __restrict__ Xs, const __half* __restrict__ W,
             float* __restrict__ C, const float* __restrict__ R)
{
    extern __shared__ __half smh[];
    dense_hmma_body(smh, Xs, W, C, R, 1, blockIdx.x, blockIdx.y);
}

// ---------------- MoE grouped GEMM (fp16 output, 2-stage) ----------------
template<int KDIM, int NDIM>
__global__ __launch_bounds__(256)
void moe_hmma(const __half* __restrict__ X, const int* __restrict__ rowmap,
              const __half* __restrict__ W, __half* __restrict__ C)
{
    constexpr int NC = KDIM / 32;
    extern __shared__ __half smh[];
    __half* Abuf = smh;
    __half* Bbuf = smh + 2*ABUFH;

    const int tid = threadIdx.x;
    const int wid = tid >> 5, lane = tid & 31;
    const int wm = wid & 1, wn = wid >> 1;
    const int m0w = wm*64, n0w = wn*64;
    const int r = lane >> 2, cq = lane & 3;

    const int e  = blockIdx.z;
    const int mt = blockIdx.y;
    const int n0 = blockIdx.x * 256;

    const int rowA = tid >> 1, segA = tid & 1;
    int token = rowmap[e*SLOTS + mt*128 + rowA];
    if (token < 0) token = 0;
    const __half* srcA = X + (size_t)token * KDIM + segA*16;
    const uint32_t smA = smem_cast(Abuf) + (uint32_t)(rowA*APH + segA*16)*2;

    const int rowB = tid;
    const __half* srcB = W + ((size_t)e*NDIM + n0 + rowB) * KDIM;
    const uint32_t smB = smem_cast(Bbuf) + (uint32_t)(rowB*BPH)*2;

    const uint32_t lmA = smem_cast(Abuf)
        + (uint32_t)(((m0w + (lane & 15))*APH + ((lane >> 4) & 1)*8) * 2);
    const uint32_t lmB = smem_cast(Bbuf)
        + (uint32_t)((((lane & 7) + ((lane >> 4) & 1)*8)*BPH + ((lane >> 3) & 1)*8) * 2);

    float acc[4][8][4];
    #pragma unroll
    for (int mi = 0; mi < 4; mi++)
        #pragma unroll
        for (int ni = 0; ni < 8; ni++)
            #pragma unroll
            for (int q = 0; q < 4; q++) acc[mi][ni][q] = 0.f;

    auto load_chunk = [&](int c) {
        uint32_t da = smA + (uint32_t)(c & 1)*(ABUFH*2);
        const __half* sa = srcA + c*32;
        CP_ASYNC16(da,      sa);
        CP_ASYNC16(da + 16, sa + 8);
        uint32_t db = smB + (uint32_t)(c & 1)*(BBUFH*2);
        const __half* sb2 = srcB + c*32;
        #pragma unroll
        for (int i = 0; i < 4; i++) CP_ASYNC16(db + i*16, sb2 + i*8);
        CP_COMMIT();
    };

    load_chunk(0);
    for (int c = 0; c < NC; c++) {
        if (c + 1 < NC) { load_chunk(c + 1); CP_WAIT(1); }
        else           { CP_WAIT(0); }
        __syncthreads();

        const uint32_t bufA = lmA + (uint32_t)(c & 1)*(ABUFH*2);
        const uint32_t bufB = lmB + (uint32_t)(c & 1)*(BBUFH*2);
        #pragma unroll
        for (int ks = 0; ks < 2; ks++) {
            uint32_t a[4][4];
            #pragma unroll
            for (int mi = 0; mi < 4; mi++)
                ldsm_x4(a[mi], bufA + (uint32_t)((mi*16*APH + ks*16)*2));
            uint32_t b[8][2];
            #pragma unroll
            for (int j = 0; j < 4; j++) {
                uint32_t rr[4];
                ldsm_x4(rr, bufB + (uint32_t)(((n0w + 16*j)*BPH + ks*16)*2));
                b[2*j  ][0] = rr[0]; b[2*j  ][1] = rr[1];
                b[2*j+1][0] = rr[2]; b[2*j+1][1] = rr[3];
            }
            #pragma unroll
            for (int mi = 0; mi < 4; mi++)
                #pragma unroll
                for (int ni = 0; ni < 8; ni++)
                    mma_f16(acc[mi][ni], a[mi], b[ni]);
        }
        __syncthreads();
    }

    #pragma unroll
    for (int mi = 0; mi < 4; mi++) {
        int mrow = mt*128 + m0w + mi*16 + r;
        __half* C0 = C + ((size_t)e*SLOTS + mrow    )*NDIM + n0 + n0w;
        __half* C1 = C + ((size_t)e*SLOTS + mrow + 8)*NDIM + n0 + n0w;
        #pragma unroll
        for (int ni = 0; ni < 8; ni++) {
            int col = ni*8 + 2*cq;
            *(__half2*)(C0 + col) = __floats2half2_rn(acc[mi][ni][0], acc[mi][ni][1]);
            *(__half2*)(C1 + col) = __floats2half2_rn(acc[mi][ni][2], acc[mi][ni][3]);
        }
    }
}

// ---------------- split-KV attention (1 thread/query) ----------------
__global__ __launch_bounds__(64)
void attn_split_kernel(const float* __restrict__ Q, const float* __restrict__ K,
                       const float* __restrict__ V,
                       float* __restrict__ opart, float* __restrict__ ml)
{
    __shared__ float Ks[2][32][64];
    __shared__ float Vs[2][32][64];
    const int bh = blockIdx.y;
    const int b = bh / NH, h = bh % NH;
    const int split = blockIdx.z;
    const int qi = blockIdx.x*64 + threadIdx.x;
    const int row = b*SEQ + qi;
    const size_t qoff = (size_t)row*DM + h*64;
    const size_t kbase = ((size_t)b*SEQ)*DM + h*64;

    const uint32_t sK = smem_cast(Ks);
    const uint32_t sV = smem_cast(Vs);

    u64 q2[32];
    #pragma unroll
    for (int d = 0; d < 64; d += 4) {
        float4 t = *(const float4*)&Q[qoff + d];
        q2[d/2]   = pack2(t.x*0.125f, t.y*0.125f);
        q2[d/2+1] = pack2(t.z*0.125f, t.w*0.125f);
    }
    float m = -1e30f, l = 0.f;
    u64 o2[32];
    #pragma unroll
    for (int d2 = 0; d2 < 32; d2++) o2[d2] = 0ull;

    auto load_tile = [&](int kt, int buf) {
        #pragma unroll
        for (int it = 0; it < 8; it++) {
            int f = threadIdx.x + it*64;
            int j = f >> 4; int d4 = (f & 15)*4;
            uint32_t off = (uint32_t)(buf*8192 + (j*64 + d4)*4);
            size_t src = kbase + (size_t)(kt + j)*DM + d4;
            CP_ASYNC16(sK + off, &K[src]);
            CP_ASYNC16(sV + off, &V[src]);
        }
        CP_COMMIT();
    };

    const int t0 = split * 8;
    load_tile(t0*32, 0);
    for (int t = 0; t < 8; t++) {
        const int buf = t & 1;
        if (t + 1 < 8) { load_tile((t0 + t + 1)*32, (t+1) & 1); CP_WAIT(1); }
        else           { CP_WAIT(0); }
        __syncthreads();

        float s[32];
        #pragma unroll
        for (int j = 0; j < 32; j++) {
            const uint32_t kj = sK + (uint32_t)(buf*8192 + j*256);
            u64 accA = 0ull, accB = 0ull;
            #pragma unroll
            for (int g = 0; g < 16; g++) {
                u64 x, y;
                lds_v2u64(x, y, kj + (uint32_t)(g*16));
                accA = fma2(q2[2*g],   x, accA);
                accB = fma2(q2[2*g+1], y, accB);
            }
            float2 fa = unpack2(accA), fb = unpack2(accB);
            s[j] = (fa.x + fa.y) + (fb.x + fb.y);
        }
        float tmax = m;
        #pragma unroll
        for (int j = 0; j < 32; j++) tmax = fmaxf(tmax, s[j]);
        float f = __expf(m - tmax);
        l *= f;
        u64 f2 = pack2(f, f);
        #pragma unroll
        for (int d2 = 0; d2 < 32; d2++) o2[d2] = mul2(o2[d2], f2);
        #pragma unroll
        for (int j = 0; j < 32; j++) {
            float p = __expf(s[j] - tmax);
            l += p;
            u64 p2v = pack2(p, p);
            const uint32_t vj = sV + (uint32_t)(buf*8192 + j*256);
            #pragma unroll
            for (int g = 0; g < 16; g++) {
                u64 x, y;
                lds_v2u64(x, y, vj + (uint32_t)(g*16));
                o2[2*g]   = fma2(p2v, x, o2[2*g]);
                o2[2*g+1] = fma2(p2v, y, o2[2*g+1]);
            }
        }
        m = tmax;
        __syncthreads();
    }
    float* op = opart + (size_t)split*NROWS*DM + qoff;
    #pragma unroll
    for (int d2 = 0; d2 < 32; d2 += 2) {
        float2 pa = unpack2(o2[d2]), pb = unpack2(o2[d2+1]);
        *(float4*)&op[d2*2] = make_float4(pa.x, pa.y, pb.x, pb.y);
    }
    float* mlp = ml + (((size_t)split*NROWS + row)*NH + h)*2;
    mlp[0] = m; mlp[1] = l;
}

// merge -> ctx split only (dead fp32 ctx store removed)
__global__ __launch_bounds__(512)
void attn_merge_kernel(const float* __restrict__ opart, const float* __restrict__ ml,
                       __half* __restrict__ Cs)
{
    const int row = blockIdx.x;
    const int d = threadIdx.x;
    const int h = d >> 6;
    float mm[NSPLIT], llv[NSPLIT];
    float M = -1e30f;
    #pragma unroll
    for (int s = 0; s < NSPLIT; s++) {
        const float* mlp = ml + (((size_t)s*NROWS + row)*NH + h)*2;
        mm[s] = mlp[0]; llv[s] = mlp[1];
        M = fmaxf(M, mm[s]);
    }
    float denom = 0.f, acc = 0.f;
    #pragma unroll
    for (int s = 0; s < NSPLIT; s++) {
        float sc = __expf(mm[s] - M);
        denom += llv[s] * sc;
        acc   += sc * opart[(size_t)s*NROWS*DM + (size_t)row*DM + d];
    }
    float v = acc / denom;
    __half hi = __float2half_rn(v);
    float lo = v - __half2float(hi);
    __half* cr = Cs + (size_t)row*KP3;
    cr[d] = hi; cr[512 + d] = hi; cr[1024 + d] = __float2half_rn(lo);
}

// ---------------- layernorm ----------------
__global__ void ln_kernel(const float* __restrict__ X, float* __restrict__ Y,
                          __half* __restrict__ Yh,
                          const float* __restrict__ gg, const float* __restrict__ bb, int len)
{
    __shared__ float sb[32];
    const int row = blockIdx.x;
    const float* xr = X + (size_t)row*len;
    float sum = 0.f;
    for (int c = threadIdx.x; c < len; c += blockDim.x) sum += xr[c];
    float mean = blk_sum(sum, sb) / len;
    float s2 = 0.f;
    for (int c = threadIdx.x; c < len; c += blockDim.x) { float d = xr[c]-mean; s2 += d*d; }
    float var = blk_sum(s2, sb) / len;
    float r = rsqrtf(var + EPSV);
    for (int c = threadIdx.x; c < len; c += blockDim.x) {
        float v = (xr[c]-mean)*r*gg[c] + bb[c];
        Y[(size_t)row*len + c] = v;
        if (Yh) Yh[(size_t)row*len + c] = __float2half_rn(v);
    }
}

// ---------------- gating (fp32 exact — unchanged) ----------------
__global__ void gate_kernel(const float* __restrict__ Xres, const float* __restrict__ wg)
{
    __shared__ float xr[DM];
    __shared__ float lg[NE];
    const int tt = blockIdx.x;
    const int grp = tt >> 11, ti = tt & 2047;
    const int row = ((ti >> 8) * SEQ) + grp*256 + (ti & 255);
    for (int c = threadIdx.x; c < DM; c += blockDim.x) xr[c] = Xres[(size_t)row*DM + c];
    __syncthreads();
    if (threadIdx.x < NE) {
        float acc = 0.f;
        #pragma unroll 8
        for (int d = 0; d < DM; d++) acc = fmaf(xr[d], wg[d*NE + threadIdx.x], acc);
        lg[threadIdx.x] = acc;
    }
    __syncthreads();
    if (threadIdx.x == 0) {
        int i1 = 0; float v1 = lg[0];
        for (int e2 = 1; e2 < NE; e2++) if (lg[e2] > v1) { v1 = lg[e2]; i1 = e2; }
        int i2 = -1; float v2 = -1e30f;
        for (int e2 = 0; e2 < NE; e2++) if (e2 != i1 && lg[e2] > v2) { v2 = lg[e2]; i2 = e2; }
        float r2 = expf(v2 - v1);
        float inv = 1.f / (1.f + r2);
        g_e1[tt] = i1; g_e2[tt] = i2;
        g_wa[tt] = inv; g_wb[tt] = r2 * inv;
    }
}

// ---------------- GShard slot assignment ----------------
__global__ void assign_kernel()
{
    __shared__ int scnt[NE];
    const int grp = blockIdx.x;
    const int tid = threadIdx.x, lane = tid & 31, e = tid >> 5;
    for (int i = tid; i < NE*GOFF; i += blockDim.x) {
        int ee = i / GOFF, s = i % GOFF;
        g_rowg[ee*SLOTS + grp*GOFF + s] = -1;
        g_rowl[ee*SLOTS + grp*GOFF + s] = -1;
    }
    __syncthreads();
    int cnt = 0;
    for (int base = 0; base < TG; base += 32) {
        int ti = base + lane;
        int tt = grp*TG + ti;
        bool mm = (g_e1[tt] == e);
        unsigned bal = __ballot_sync(0xffffffffu, mm);
        if (mm) {
            int loc = cnt + __popc(bal & ((1u << lane) - 1u));
            if (loc < CAP) {
                int srow = grp*GOFF + loc;
                g_s1[tt] = srow;
                int row = ((ti >> 8) * SEQ) + grp*256 + (ti & 255);
                g_rowg[e*SLOTS + srow] = row;
                g_rowl[e*SLOTS + srow] = tt;
            } else g_s1[tt] = -1;
        }
        cnt += __popc(bal);
    }
    if (lane == 0) scnt[e] = cnt;
    __syncthreads();
    cnt = scnt[e];
    for (int base = 0; base < TG; base += 32) {
        int ti = base + lane;
        int tt = grp*TG + ti;
        bool mm = (g_e2[tt] == e);
        unsigned bal = __ballot_sync(0xffffffffu, mm);
        if (mm) {
            int loc = cnt + __popc(bal & ((1u << lane) - 1u));
            if (loc < CAP) {
                int srow = grp*GOFF + loc;
                g_s2[tt] = srow;
                int row = ((ti >> 8) * SEQ) + grp*256 + (ti & 255);
                g_rowg[e*SLOTS + srow] = row;
                g_rowl[e*SLOTS + srow] = tt;
            } else g_s2[tt] = -1;
        }
        cnt += __popc(bal);
    }
}

// ---------------- combine MoE1 (fp16 slots) + bias + LN + relu -> fp16 ----------------
__global__ void combine1_kernel(const float* __restrict__ b1)
{
    __shared__ float sb[32];
    const int tt = blockIdx.x;
    const int grp = tt >> 11;
    const float* lng = g_lnp[2*grp];
    const float* lnb = g_lnp[2*grp+1];
    const int e1 = g_e1[tt], e2 = g_e2[tt], s1 = g_s1[tt], s2 = g_s2[tt];
    const float wa = g_wa[tt], wb = g_wb[tt];
    const __half* p1 = (s1 >= 0) ? &g_sloth[((size_t)e1*SLOTS + s1)*DI] : (const __half*)0;
    const __half* p2 = (s2 >= 0) ? &g_sloth[((size_t)e2*SLOTS + s2)*DI] : (const __half*)0;
    float vals[8];
    float sum = 0.f;
    #pragma unroll
    for (int i = 0; i < 8; i++) {
        int c = threadIdx.x + i*256;
        float hv = 0.f;
        if (p1) hv += wa * (__half2float(p1[c]) + b1[e1*DI + c]);
        if (p2) hv += wb * (__half2float(p2[c]) + b1[e2*DI + c]);
        vals[i] = hv; sum += hv;
    }
    float mean = blk_sum(sum, sb) / DI;
    float s2s = 0.f;
    #pragma unroll
    for (int i = 0; i < 8; i++) { float d = vals[i]-mean; s2s += d*d; }
    float var = blk_sum(s2s, sb) / DI;
    float r = rsqrtf(var + EPSV);
    #pragma unroll
    for (int i = 0; i < 8; i++) {
        int c = threadIdx.x + i*256;
        float v = fmaxf((vals[i]-mean)*r*lng[c] + lnb[c], 0.f);
        g_hpost[(size_t)tt*DI + c] = __float2half_rn(v);
    }
}

// ---------------- combine MoE2 (fp16 slots) + bias + residual + FINAL LN ----------------
__global__ void combine2_ln_kernel(const float* __restrict__ b2, float* __restrict__ out,
                                   const float* __restrict__ gg, const float* __restrict__ bb)
{
    __shared__ float sb[32];
    const int tt = blockIdx.x;
    const int grp = tt >> 11, ti = tt & 2047;
    const int e1 = g_e1[tt], e2 = g_e2[tt], s1 = g_s1[tt], s2 = g_s2[tt];
    const float wa = g_wa[tt], wb = g_wb[tt];
    const int row = ((ti >> 8) * SEQ) + grp*256 + (ti & 255);
    float vals[4];
    float sum = 0.f;
    #pragma unroll
    for (int i = 0; i < 4; i++) {
        int c = threadIdx.x + i*128;
        float y = 0.f;
        if (s1 >= 0) y += wa * (__half2float(g_sloty[((size_t)e1*SLOTS + s1)*DM + c]) + b2[e1*DM + c]);
        if (s2 >= 0) y += wb * (__half2float(g_sloty[((size_t)e2*SLOTS + s2)*DM + c]) + b2[e2*DM + c]);
        y += g_res[(size_t)row*DM + c];
        vals[i] = y; sum += y;
    }
    float mean = blk_sum(sum, sb) / DM;
    float s2s = 0.f;
    #pragma unroll
    for (int i = 0; i < 4; i++) { float d = vals[i]-mean; s2s += d*d; }
    float var = blk_sum(s2s, sb) / DM;
    float r = rsqrtf(var + EPSV);
    #pragma unroll
    for (int i = 0; i < 4; i++) {
        int c = threadIdx.x + i*128;
        out[(size_t)row*DM + c] = (vals[i]-mean)*r*gg[c] + bb[c];
    }
}

__global__ void set_lnp_kernel(const float* a0, const float* a1, const float* a2, const float* a3,
                               const float* a4, const float* a5, const float* a6, const float* a7)
{
    g_lnp[0]=a0; g_lnp[1]=a1; g_lnp[2]=a2; g_lnp[3]=a3;
    g_lnp[4]=a4; g_lnp[5]=a5; g_lnp[6]=a6; g_lnp[7]=a7;
}

// ---------------- launch ----------------
extern "C" void kernel_launch(void* const* d_in, const int* in_sizes, int n_in,
                              void* d_out, int out_size)
{
    const float *x=0,*wq=0,*wk=0,*wv=0,*wo=0,*ln_attn_g=0,*ln_attn_b=0,*wg1=0,*w1=0,*b1=0,
                *w2=0,*b2=0,*ln_out_g=0,*ln_out_b=0;
    const float* ln2048[8] = {0,0,0,0,0,0,0,0};
    int c262=0,c512=0,c12k=0,c25m=0,c49k=0,c2k=0;
    for (int i = 0; i < n_in; i++) {
        const float* p = (const float*)d_in[i];
        switch (in_sizes[i]) {
            case 4194304: x = p; break;
            case 262144:
                if (c262==0) wq=p; else if (c262==1) wk=p; else if (c262==2) wv=p; else wo=p;
                c262++; break;
            case 512:
                if (c512==0) ln_attn_g=p; else if (c512==1) ln_attn_b=p;
                else if (c512==2) ln_out_g=p; else ln_out_b=p;
                c512++; break;
            case 12288:
                if (c12k==0) wg1=p; else b2=p;
                c12k++; break;
            case 25165824:
                if (c25m==0) w1=p; else w2=p;
                c25m++; break;
            case 49152:
                if (c49k==0) b1=p;
                c49k++; break;
            case 2048:
                if (c2k < 8) ln2048[c2k] = p;
                c2k++; break;
            default: break;
        }
    }

    float *p_q,*p_k,*p_v,*p_tmp,*p_res,*p_part,*p_ml;
    __half *p_resh,*p_xs,*p_cs,*p_wqs,*p_wks,*p_wvs,*p_wos,*p_wh1,*p_wh2,*p_sloth,*p_sloty,*p_hpost;
    int *p_rowg,*p_rowl;
    cudaGetSymbolAddress((void**)&p_q,     g_q);
    cudaGetSymbolAddress((void**)&p_k,     g_k);
    cudaGetSymbolAddress((void**)&p_v,     g_v);
    cudaGetSymbolAddress((void**)&p_tmp,   g_tmp);
    cudaGetSymbolAddress((void**)&p_res,   g_res);
    cudaGetSymbolAddress((void**)&p_resh,  g_resh);
    cudaGetSymbolAddress((void**)&p_part,  g_part);
    cudaGetSymbolAddress((void**)&p_ml,    g_ml);
    cudaGetSymbolAddress((void**)&p_xs,    g_xs);
    cudaGetSymbolAddress((void**)&p_cs,    g_cs);
    cudaGetSymbolAddress((void**)&p_wqs,   g_wqs);
    cudaGetSymbolAddress((void**)&p_wks,   g_wks);
    cudaGetSymbolAddress((void**)&p_wvs,   g_wvs);
    cudaGetSymbolAddress((void**)&p_wos,   g_wos);
    cudaGetSymbolAddress((void**)&p_wh1,   g_wh1);
    cudaGetSymbolAddress((void**)&p_wh2,   g_wh2);
    cudaGetSymbolAddress((void**)&p_sloth, g_sloth);
    cudaGetSymbolAddress((void**)&p_sloty, g_sloty);
    cudaGetSymbolAddress((void**)&p_hpost, g_hpost);
    cudaGetSymbolAddress((void**)&p_rowg,  g_rowg);
    cudaGetSymbolAddress((void**)&p_rowl,  g_rowl);

    float* out = (float*)d_out;

    cudaFuncSetAttribute(moe_hmma<DM, DI>, cudaFuncAttributeMaxDynamicSharedMemorySize, HMMA_SMEM_BYTES);
    cudaFuncSetAttribute(moe_hmma<DI, DM>, cudaFuncAttributeMaxDynamicSharedMemorySize, HMMA_SMEM_BYTES);
    cudaFuncSetAttribute(qkv_hmma, cudaFuncAttributeMaxDynamicSharedMemorySize, HMMA_SMEM_BYTES);
    cudaFuncSetAttribute(wo_hmma,  cudaFuncAttributeMaxDynamicSharedMemorySize, HMMA_SMEM_BYTES);

    static cudaStream_t s2 = 0;
    static cudaEvent_t evFork = 0, evJoin = 0;
    if (!s2) {
        cudaStreamCreateWithFlags(&s2, cudaStreamNonBlocking);
        cudaEventCreateWithFlags(&evFork, cudaEventDisableTiming);
        cudaEventCreateWithFlags(&evJoin, cudaEventDisableTiming);
    }

    // 0a) fork: MoE weight transposes on side stream
    cudaEventRecord(evFork, 0);
    cudaStreamWaitEvent(s2, evFork, 0);
    transpose_half<<<dim3(DI/32, DM/32, NE), dim3(32,8), 0, s2>>>(w1, p_wh1, DM, DI);
    transpose_half<<<dim3(DM/32, DI/32, NE), dim3(32,8), 0, s2>>>(w2, p_wh2, DI, DM);
    cudaEventRecord(evJoin, s2);

    // 0b) main-stream prep
    split_wt<<<dim3(16,16), dim3(32,8)>>>(wq, p_wqs);
    split_wt<<<dim3(16,16), dim3(32,8)>>>(wk, p_wks);
    split_wt<<<dim3(16,16), dim3(32,8)>>>(wv, p_wvs);
    split_wt<<<dim3(16,16), dim3(32,8)>>>(wo, p_wos);
    split_acts<<<(NROWS*DM)/256, 256>>>(x, p_xs);
    set_lnp_kernel<<<1,1>>>(ln2048[0],ln2048[1],ln2048[2],ln2048[3],
                            ln2048[4],ln2048[5],ln2048[6],ln2048[7]);

    // 1) QKV projections
    qkv_hmma<<<dim3(DM/256, NROWS/128, 3), 256, HMMA_SMEM_BYTES>>>(
        p_xs, p_wqs, p_wks, p_wvs, p_q, p_k, p_v);

    // 2) attention: split-KV x4 + merge (emits ctx split only)
    attn_split_kernel<<<dim3(SEQ/64, NB*NH, NSPLIT), 64>>>(p_q, p_k, p_v, p_part, p_ml);
    attn_merge_kernel<<<NROWS, 512>>>(p_part, p_ml, p_cs);

    // 3) output projection + LN
    wo_hmma<<<dim3(DM/256, NROWS/128), 256, HMMA_SMEM_BYTES>>>(p_cs, p_wos, p_tmp, x);
    ln_kernel<<<NROWS, 256>>>(p_tmp, p_res, p_resh, ln_attn_g, ln_attn_b, DM);

    // 4) routing
    gate_kernel<<<NTOK, 128>>>(p_res, wg1);
    assign_kernel<<<NGRP, NE*32>>>();

    // join side stream before MoE consumes transposed weights
    cudaStreamWaitEvent(0, evJoin, 0);

    // 5) MoE (fp16 slot buffers)
    moe_hmma<DM, DI><<<dim3(DI/256, SLOTS/128, NE), 256, HMMA_SMEM_BYTES>>>(p_resh, p_rowg, p_wh1, p_sloth);
    combine1_kernel<<<NTOK, 256>>>(b1);
    moe_hmma<DI, DM><<<dim3(DM/256, SLOTS/128, NE), 256, HMMA_SMEM_BYTES>>>(p_hpost, p_rowl, p_wh2, p_sloty);
    combine2_ln_kernel<<<NTOK, 128>>>(b2, out, ln_out_g, ln_out_b);

    (void)out_size;
}